// round 5
// baseline (speedup 1.0000x reference)
#include <cuda_runtime.h>

#define TLEN 4096
#define BROWS 2048
#define SHIFTW 10
#define NSHIFT 21
#define THREADS 256
#define QUADS_PER_THREAD (TLEN / (THREADS * 4))

__device__ float g_row_mse[BROWS];
__device__ unsigned int g_done = 0;

__global__ __launch_bounds__(THREADS, 4) void shift_loss_kernel(
    const float* __restrict__ x, const float* __restrict__ y,
    float* __restrict__ out)
{
    const int row = blockIdx.x;
    const float* __restrict__ xr = x + (size_t)row * TLEN;
    const float* __restrict__ yr = y + (size_t)row * TLEN;
    const int tid = threadIdx.x;
    const int lane = tid & 31;

    __shared__ float red[THREADS / 32][25];
    __shared__ float tot[25];
    __shared__ float corr_sh[NSHIFT];
    __shared__ float mse_sh[NSHIFT];
    __shared__ int is_last_sh;

    float acc[NSHIFT];
#pragma unroll
    for (int s = 0; s < NSHIFT; ++s) acc[s] = 0.f;
    float sx = 0.f, sxx = 0.f, sy = 0.f, syy = 0.f;

#pragma unroll
    for (int it = 0; it < QUADS_PER_THREAD; ++it) {
        const int t0 = (it * THREADS + tid) * 4;

        // own quads (fully coalesced; every byte of x,y loaded exactly once)
        const float4 xv = *reinterpret_cast<const float4*>(xr + t0);
        const float4 yv = *reinterpret_cast<const float4*>(yr + t0);
        float xk[4] = {xv.x, xv.y, xv.z, xv.w};
        float yq[4] = {yv.x, yv.y, yv.z, yv.w};

#pragma unroll
        for (int k = 0; k < 4; ++k) { sx += xk[k]; sxx += xk[k] * xk[k]; }
#pragma unroll
        for (int c = 0; c < 4; ++c) { sy += yq[c]; syy += yq[c] * yq[c]; }

        // window w[i] = y[t0-12+i], i=0..27. Quad j (=d+3) comes from lane+d's yq.
        // d=0 (j=3) is the own quad. Edge lanes fall back to direct loads.
#pragma unroll
        for (int j = 0; j < 7; ++j) {
            const int d = j - 3;
            float w4[4];
            if (d == 0) {
#pragma unroll
                for (int c = 0; c < 4; ++c) w4[c] = yq[c];
            } else {
                const int sl = lane + d;
#pragma unroll
                for (int c = 0; c < 4; ++c)
                    w4[c] = __shfl_sync(0xffffffffu, yq[c], sl);
                if (sl < 0 || sl > 31) {  // warp-edge lanes: real load (zero-padded)
                    const int base = t0 + 4 * d;
                    if (base >= 0 && base + 4 <= TLEN) {
                        const float4 v = *reinterpret_cast<const float4*>(yr + base);
                        w4[0] = v.x; w4[1] = v.y; w4[2] = v.z; w4[3] = v.w;
                    } else {
#pragma unroll
                        for (int c = 0; c < 4; ++c) {
                            const int yi = base + c;
                            w4[c] = (yi >= 0 && yi < TLEN) ? yr[yi] : 0.f;
                        }
                    }
                }
            }
            // w[i] feeds acc[i-k-2]; i = 4j+c  (all indices compile-time)
#pragma unroll
            for (int c = 0; c < 4; ++c) {
                const int i = 4 * j + c;
#pragma unroll
                for (int k = 0; k < 4; ++k) {
                    const int s = i - k - 2;
                    if (s >= 0 && s < NSHIFT)
                        acc[s] += xk[k] * w4[c];
                }
            }
        }
    }

    // ---- block reduction of 25 partials ----
    float vals[25];
    vals[0] = sx; vals[1] = sxx; vals[2] = sy; vals[3] = syy;
#pragma unroll
    for (int s = 0; s < NSHIFT; ++s) vals[4 + s] = acc[s];

#pragma unroll
    for (int i = 0; i < 25; ++i) {
#pragma unroll
        for (int o = 16; o > 0; o >>= 1)
            vals[i] += __shfl_down_sync(0xffffffffu, vals[i], o);
    }
    const int wid = tid >> 5;
    if (lane == 0) {
#pragma unroll
        for (int i = 0; i < 25; ++i) red[wid][i] = vals[i];
    }
    __syncthreads();
    if (tid < 25) {
        float t = 0.f;
#pragma unroll
        for (int wb = 0; wb < THREADS / 32; ++wb) t += red[wb][tid];
        tot[tid] = t;
    }
    __syncthreads();

    // ---- 21 threads: per-shift trimmed Pearson + MSE ----
    if (tid < NSHIFT) {
        const int sh = tid - SHIFTW;
        float Sx = tot[0], Sxx = tot[1], Sy = tot[2], Syy = tot[3];
        const int m = sh < 0 ? -sh : sh;
        const float n = (float)(TLEN - m);
        if (sh > 0) {
            for (int i = 0; i < sh; ++i) {
                const float xv2 = xr[TLEN - 1 - i]; Sx -= xv2; Sxx -= xv2 * xv2;
                const float yv2 = yr[i];            Sy -= yv2; Syy -= yv2 * yv2;
            }
        } else if (sh < 0) {
            for (int i = 0; i < m; ++i) {
                const float xv2 = xr[i];            Sx -= xv2; Sxx -= xv2 * xv2;
                const float yv2 = yr[TLEN - 1 - i]; Sy -= yv2; Syy -= yv2 * yv2;
            }
        }
        const float Sxy = tot[4 + tid];
        const float inv_n = 1.f / n;
        const float cov = Sxy - Sx * Sy * inv_n;
        const float vx  = Sxx - Sx * Sx * inv_n;
        const float vy  = Syy - Sy * Sy * inv_n;
        corr_sh[tid] = cov * rsqrtf(vx * vy);
        mse_sh[tid]  = (Sxx + Syy - 2.f * Sxy) * inv_n;
    }
    __syncthreads();

    if (tid == 0) {
        float best = corr_sh[0];
        int bi = 0;
#pragma unroll
        for (int s = 1; s < NSHIFT; ++s) {
            if (corr_sh[s] > best) { best = corr_sh[s]; bi = s; }  // first-max tie-break
        }
        g_row_mse[row] = mse_sh[bi];
        __threadfence();
        const unsigned int prev = atomicAdd(&g_done, 1u);
        is_last_sh = (prev == BROWS - 1u) ? 1 : 0;
    }
    __syncthreads();

    // ---- last block: fused final mean (deterministic fixed-order sum) ----
    if (is_last_sh) {
        float s = 0.f;
#pragma unroll
        for (int i = 0; i < BROWS / THREADS; ++i)
            s += __ldcg(&g_row_mse[i * THREADS + tid]);
#pragma unroll
        for (int o = 16; o > 0; o >>= 1) s += __shfl_down_sync(0xffffffffu, s, o);
        if (lane == 0) red[wid][0] = s;
        __syncthreads();
        if (tid == 0) {
            float t = 0.f;
#pragma unroll
            for (int wb = 0; wb < THREADS / 32; ++wb) t += red[wb][0];
            out[0] = t / (float)BROWS;
            g_done = 0;  // reset for next graph replay
        }
    }
}

extern "C" void kernel_launch(void* const* d_in, const int* in_sizes, int n_in,
                              void* d_out, int out_size)
{
    const float* x = (const float*)d_in[0];
    const float* y = (const float*)d_in[1];
    shift_loss_kernel<<<BROWS, THREADS>>>(x, y, (float*)d_out);
}

// round 7
// speedup vs baseline: 1.1484x; 1.1484x over previous
#include <cuda_runtime.h>

#define TLEN 4096
#define BROWS 2048
#define SHIFTW 10
#define NSHIFT 21
#define THREADS 256
#define QUADS_PER_THREAD (TLEN / (THREADS * 4))
#define HALO 12

__device__ float g_row_mse[BROWS];
__device__ unsigned int g_done = 0;

__global__ __launch_bounds__(THREADS, 5) void shift_loss_kernel(
    const float* __restrict__ x, const float* __restrict__ y,
    float* __restrict__ out)
{
    const int row = blockIdx.x;
    const float* __restrict__ xr = x + (size_t)row * TLEN;
    const float* __restrict__ yr = y + (size_t)row * TLEN;
    const int tid = threadIdx.x;
    const int lane = tid & 31;
    const int wid = tid >> 5;

    __shared__ float ys[HALO + TLEN + HALO + 4];   // zero-padded y row
    __shared__ float red[THREADS / 32][25];
    __shared__ float tot[25];
    __shared__ float corr_sh[NSHIFT];
    __shared__ float mse_sh[NSHIFT];
    __shared__ int is_last_sh;

    // ---- stage y row into smem with zero halos (coalesced, each byte once) ----
    if (tid < HALO) {
        ys[tid] = 0.f;
        ys[HALO + TLEN + tid] = 0.f;
    }
#pragma unroll
    for (int it = 0; it < QUADS_PER_THREAD; ++it) {
        const int t0 = (it * THREADS + tid) * 4;
        const float4 v = *reinterpret_cast<const float4*>(yr + t0);
        *reinterpret_cast<float4*>(&ys[HALO + t0]) = v;   // byte off 48+16k: aligned
    }
    __syncthreads();

    float acc[NSHIFT];
#pragma unroll
    for (int s = 0; s < NSHIFT; ++s) acc[s] = 0.f;
    float sx = 0.f, sxx = 0.f, sy = 0.f, syy = 0.f;

#pragma unroll
    for (int it = 0; it < QUADS_PER_THREAD; ++it) {
        const int t0 = (it * THREADS + tid) * 4;

        const float4 xv = *reinterpret_cast<const float4*>(xr + t0);
        float xk[4] = {xv.x, xv.y, xv.z, xv.w};
#pragma unroll
        for (int k = 0; k < 4; ++k) { sx += xk[k]; sxx += xk[k] * xk[k]; }

        // window w[i] = y[t0-12+i] = ys[t0 + i] (HALO cancels the -12);
        // 7 conflict-free LDS.128, zero halo = validity mask, no predicates.
#pragma unroll
        for (int j = 0; j < 7; ++j) {
            const float4 v = *reinterpret_cast<const float4*>(&ys[t0 + 4 * j]);
            float w4[4] = {v.x, v.y, v.z, v.w};
            if (j == 3) {  // own y quad y[t0..t0+3]
#pragma unroll
                for (int c = 0; c < 4; ++c) { sy += w4[c]; syy += w4[c] * w4[c]; }
            }
#pragma unroll
            for (int c = 0; c < 4; ++c) {
                const int i = 4 * j + c;
#pragma unroll
                for (int k = 0; k < 4; ++k) {
                    const int s = i - k - 2;       // compile-time after unroll
                    if (s >= 0 && s < NSHIFT)
                        acc[s] += xk[k] * w4[c];
                }
            }
        }
    }

    // ---- block reduction of 25 partials ----
    float vals[25];
    vals[0] = sx; vals[1] = sxx; vals[2] = sy; vals[3] = syy;
#pragma unroll
    for (int s = 0; s < NSHIFT; ++s) vals[4 + s] = acc[s];

#pragma unroll
    for (int i = 0; i < 25; ++i) {
#pragma unroll
        for (int o = 16; o > 0; o >>= 1)
            vals[i] += __shfl_down_sync(0xffffffffu, vals[i], o);
    }
    if (lane == 0) {
#pragma unroll
        for (int i = 0; i < 25; ++i) red[wid][i] = vals[i];
    }
    __syncthreads();
    if (tid < 25) {
        float t = 0.f;
#pragma unroll
        for (int wb = 0; wb < THREADS / 32; ++wb) t += red[wb][tid];
        tot[tid] = t;
    }
    __syncthreads();

    // ---- 21 threads: per-shift trimmed Pearson + MSE ----
    if (tid < NSHIFT) {
        const int sh = tid - SHIFTW;
        float Sx = tot[0], Sxx = tot[1], Sy = tot[2], Syy = tot[3];
        const int m = sh < 0 ? -sh : sh;
        const float n = (float)(TLEN - m);
        if (sh > 0) {
            for (int i = 0; i < sh; ++i) {
                const float xv2 = xr[TLEN - 1 - i]; Sx -= xv2; Sxx -= xv2 * xv2;
                const float yv2 = ys[HALO + i];     Sy -= yv2; Syy -= yv2 * yv2;
            }
        } else if (sh < 0) {
            for (int i = 0; i < m; ++i) {
                const float xv2 = xr[i];                   Sx -= xv2; Sxx -= xv2 * xv2;
                const float yv2 = ys[HALO + TLEN - 1 - i]; Sy -= yv2; Syy -= yv2 * yv2;
            }
        }
        const float Sxy = tot[4 + tid];
        const float inv_n = 1.f / n;
        const float cov = Sxy - Sx * Sy * inv_n;
        const float vx  = Sxx - Sx * Sx * inv_n;
        const float vy  = Syy - Sy * Sy * inv_n;
        corr_sh[tid] = cov * rsqrtf(vx * vy);
        mse_sh[tid]  = (Sxx + Syy - 2.f * Sxy) * inv_n;
    }
    __syncthreads();

    if (tid == 0) {
        float best = corr_sh[0];
        int bi = 0;
#pragma unroll
        for (int s = 1; s < NSHIFT; ++s) {
            if (corr_sh[s] > best) { best = corr_sh[s]; bi = s; }  // first-max tie-break
        }
        g_row_mse[row] = mse_sh[bi];
        __threadfence();
        const unsigned int prev = atomicAdd(&g_done, 1u);
        is_last_sh = (prev == BROWS - 1u) ? 1 : 0;
    }
    __syncthreads();

    // ---- last block: fused final mean (deterministic fixed-order sum) ----
    if (is_last_sh) {
        float s = 0.f;
#pragma unroll
        for (int i = 0; i < BROWS / THREADS; ++i)
            s += __ldcg(&g_row_mse[i * THREADS + tid]);
#pragma unroll
        for (int o = 16; o > 0; o >>= 1) s += __shfl_down_sync(0xffffffffu, s, o);
        if (lane == 0) red[wid][0] = s;
        __syncthreads();
        if (tid == 0) {
            float t = 0.f;
#pragma unroll
            for (int wb = 0; wb < THREADS / 32; ++wb) t += red[wb][0];
            out[0] = t / (float)BROWS;
            g_done = 0;  // reset for next graph replay
        }
    }
}

extern "C" void kernel_launch(void* const* d_in, const int* in_sizes, int n_in,
                              void* d_out, int out_size)
{
    const float* x = (const float*)d_in[0];
    const float* y = (const float*)d_in[1];
    shift_loss_kernel<<<BROWS, THREADS>>>(x, y, (float*)d_out);
}